// round 2
// baseline (speedup 1.0000x reference)
#include <cuda_runtime.h>
#include <cstdint>

#define D        32768   // row length
#define NT       1024    // threads per CTA
#define EPT      32      // elements per thread
#define F4PT     8       // float4 loads per thread
#define TOPK     32u

// order-preserving float -> uint key (larger float => larger key)
__device__ __forceinline__ unsigned f2k(float f) {
    unsigned u = __float_as_uint(f);
    return (u & 0x80000000u) ? ~u : (u | 0x80000000u);
}

// warp0-only: given 256-bin histogram and remaining count kk, find the byte b
// such that suffix_count(b) >= kk > suffix_count(b+1). Writes sh_b (byte),
// sh_kk (remaining among == b), sh_ce (count at bin b).
__device__ __forceinline__ void select_byte(const unsigned* hist, unsigned kk,
                                            unsigned* sh_b, unsigned* sh_kk,
                                            unsigned* sh_ce, int lane) {
    int base = lane * 8;
    unsigned s = 0;
#pragma unroll
    for (int j = 0; j < 8; ++j) s += hist[base + j];
    // inclusive suffix scan of the 32 chunk sums
    unsigned suf = s;
#pragma unroll
    for (int off = 1; off < 32; off <<= 1) {
        unsigned t = __shfl_down_sync(0xffffffffu, suf, off);
        if (lane + off < 32) suf += t;
    }
    unsigned sufnext = __shfl_down_sync(0xffffffffu, suf, 1);
    if (lane == 31) sufnext = 0;
    if (suf >= kk && sufnext < kk) {           // exactly one lane enters
        unsigned acc = sufnext;
#pragma unroll
        for (int j = 7; j >= 0; --j) {
            unsigned t = hist[base + j];
            if (acc + t >= kk) {
                *sh_b  = (unsigned)(base + j);
                *sh_kk = kk - acc;
                *sh_ce = t;
                break;
            }
            acc += t;
        }
    }
}

__global__ void __launch_bounds__(NT, 1)
topk_mask_kernel(const float* __restrict__ x, float* __restrict__ out) {
    __shared__ unsigned warp_hist[32][256];   // 32 KB, round-0 privatized
    __shared__ unsigned hist2[256];
    __shared__ unsigned sh_b, sh_kk, sh_ce;
    __shared__ unsigned sh_red[33];

    const int tid  = threadIdx.x;
    const int lane = tid & 31;
    const int wid  = tid >> 5;

    const size_t rowbase = (size_t)blockIdx.x * D;
    const float4* src = (const float4*)(x + rowbase);
    float4*       dst = (float4*)(out + rowbase);

    // ---- load entire row into registers (coalesced, streaming) ----
    float vals[EPT];
#pragma unroll
    for (int i = 0; i < F4PT; ++i) {
        float4 t = __ldcs(src + i * NT + tid);
        vals[4 * i + 0] = t.x;
        vals[4 * i + 1] = t.y;
        vals[4 * i + 2] = t.z;
        vals[4 * i + 3] = t.w;
    }

    // ---- zero histograms ----
    unsigned* wh = &warp_hist[0][0];
#pragma unroll
    for (int j = 0; j < 8; ++j) wh[tid * 8 + j] = 0;
    if (tid < 256) hist2[tid] = 0;
    __syncthreads();

    // ---- round 0: per-warp privatized histogram of top byte (no atomics) ----
#pragma unroll
    for (int e = 0; e < EPT; ++e) {
        unsigned bin  = f2k(vals[e]) >> 24;
        unsigned mask = __match_any_sync(0xffffffffu, bin);
        if ((unsigned)lane == (unsigned)(__ffs(mask) - 1))
            warp_hist[wid][bin] += __popc(mask);
    }
    __syncthreads();

    // reduce 32 warp histograms into hist2
    if (tid < 256) {
        unsigned s = 0;
#pragma unroll
        for (int w = 0; w < 32; ++w) s += warp_hist[w][tid];
        hist2[tid] = s;
    }
    __syncthreads();

    unsigned kk = TOPK;
    unsigned prefix = 0;

    if (wid == 0) select_byte(hist2, kk, &sh_b, &sh_kk, &sh_ce, lane);
    __syncthreads();
    prefix |= (sh_b << 24);
    kk = sh_kk;

    // ---- rounds 1..3: only prefix-matching elements participate (few) ----
#pragma unroll
    for (int rr = 1; rr < 4; ++rr) {
        const int shift = 24 - 8 * rr;
        if (tid < 256) hist2[tid] = 0;
        __syncthreads();
        const unsigned pref_hi = prefix >> (shift + 8);
#pragma unroll
        for (int e = 0; e < EPT; ++e) {
            unsigned k = f2k(vals[e]);
            if ((k >> (shift + 8)) == pref_hi)
                atomicAdd(&hist2[(k >> shift) & 0xFFu], 1u);
        }
        __syncthreads();
        if (wid == 0) select_byte(hist2, kk, &sh_b, &sh_kk, &sh_ce, lane);
        __syncthreads();
        prefix |= (sh_b << shift);
        kk = sh_kk;
    }

    const unsigned K  = prefix;   // exact 32nd-largest key
    const unsigned m  = kk;       // how many == K to keep
    const unsigned ce = sh_ce;    // how many == K exist

    // ---- tie handling (rare): keep the m lowest indices among == K ----
    unsigned T = 0xFFFFFFFFu;     // index cutoff (inclusive)
    if (m != ce) {                // block-uniform condition (shared values)
        unsigned lo = 0, hi = D - 1;
        while (lo < hi) {
            unsigned mid = (lo + hi) >> 1;
            unsigned c = 0;
#pragma unroll
            for (int e = 0; e < EPT; ++e) {
                unsigned k   = f2k(vals[e]);
                unsigned idx = (unsigned)(((e >> 2) * NT + tid) * 4 + (e & 3));
                if (k == K && idx <= mid) c++;
            }
#pragma unroll
            for (int off = 16; off; off >>= 1)
                c += __shfl_xor_sync(0xffffffffu, c, off);
            if (lane == 0) sh_red[wid] = c;
            __syncthreads();
            if (wid == 0) {
                unsigned t = sh_red[lane];
#pragma unroll
                for (int off = 16; off; off >>= 1)
                    t += __shfl_xor_sync(0xffffffffu, t, off);
                if (lane == 0) sh_red[32] = t;
            }
            __syncthreads();
            c = sh_red[32];
            if (c >= m) hi = mid; else lo = mid + 1;
        }
        T = lo;
    }

    // ---- masked write, fully coalesced float4 streaming stores ----
#pragma unroll
    for (int i = 0; i < F4PT; ++i) {
        float4 o;
        float f; unsigned k, idx; bool keep;

        f = vals[4 * i + 0]; k = f2k(f);
        idx = (unsigned)((i * NT + tid) * 4 + 0);
        keep = (k > K) || (k == K && idx <= T);
        o.x = keep ? f : 0.0f;

        f = vals[4 * i + 1]; k = f2k(f);
        idx = (unsigned)((i * NT + tid) * 4 + 1);
        keep = (k > K) || (k == K && idx <= T);
        o.y = keep ? f : 0.0f;

        f = vals[4 * i + 2]; k = f2k(f);
        idx = (unsigned)((i * NT + tid) * 4 + 2);
        keep = (k > K) || (k == K && idx <= T);
        o.z = keep ? f : 0.0f;

        f = vals[4 * i + 3]; k = f2k(f);
        idx = (unsigned)((i * NT + tid) * 4 + 3);
        keep = (k > K) || (k == K && idx <= T);
        o.w = keep ? f : 0.0f;

        __stcs(dst + i * NT + tid, o);
    }
}

extern "C" void kernel_launch(void* const* d_in, const int* in_sizes, int n_in,
                              void* d_out, int out_size) {
    const float* x = (const float*)d_in[0];
    float* out = (float*)d_out;
    int rows = in_sizes[0] / D;
    if (rows <= 0) return;
    topk_mask_kernel<<<rows, NT>>>(x, out);
}

// round 3
// speedup vs baseline: 1.9383x; 1.9383x over previous
#include <cuda_runtime.h>
#include <cstdint>

#define D     32768          // row length
#define NT    512            // threads per CTA
#define NW    16             // warps per CTA
#define NF4   16             // float4 loads per thread (512*16*4 = 32768)
#define TOPK  32u
#define CAP   128            // candidate list capacity (Gaussian needs ~2-8)

struct SmemLayout {
    uint2          keys16[D / 4];      // 64 KB: packed top-16-bit keys (4 u16 per uint2)
    unsigned short whist[NW][256];     // 8 KB: per-warp privatized round-0 hist
    unsigned       hist2[256];         // 1 KB
    unsigned       ckey[CAP];
    unsigned       cidx[CAP];
    unsigned       nc;
    unsigned       sh_b, sh_kk, sh_ce;
    unsigned       sh_K, sh_T;
    unsigned       sh_red[NW + 1];
};

// order-preserving float -> uint key (larger float => larger key)
__device__ __forceinline__ unsigned f2k(float f) {
    unsigned u = __float_as_uint(f);
    return (u & 0x80000000u) ? ~u : (u | 0x80000000u);
}
// exact inverse
__device__ __forceinline__ float k2f(unsigned k) {
    return (k & 0x80000000u) ? __uint_as_float(k & 0x7FFFFFFFu)
                             : __uint_as_float(~k);
}

// warp0-only: pick byte b with suffix_count(b) >= kk > suffix_count(b+1).
__device__ __forceinline__ void select_byte(const unsigned* hist, unsigned kk,
                                            unsigned* sh_b, unsigned* sh_kk,
                                            unsigned* sh_ce, int lane) {
    int base = lane * 8;
    unsigned s = 0;
#pragma unroll
    for (int j = 0; j < 8; ++j) s += hist[base + j];
    unsigned suf = s;
#pragma unroll
    for (int off = 1; off < 32; off <<= 1) {
        unsigned t = __shfl_down_sync(0xffffffffu, suf, off);
        if (lane + off < 32) suf += t;
    }
    unsigned sufnext = __shfl_down_sync(0xffffffffu, suf, 1);
    if (lane == 31) sufnext = 0;
    if (suf >= kk && sufnext < kk) {   // exactly one lane
        unsigned acc = sufnext;
#pragma unroll
        for (int j = 7; j >= 0; --j) {
            unsigned t = hist[base + j];
            if (acc + t >= kk) {
                *sh_b  = (unsigned)(base + j);
                *sh_kk = kk - acc;
                *sh_ce = t;
                break;
            }
            acc += t;
        }
    }
}

__device__ __forceinline__ float keepv(float f, unsigned idx,
                                       unsigned K, unsigned T, float thrF) {
    // fast reject: k > K implies f >= thrF in IEEE order (0-cases land in ==)
    if (!(f >= thrF)) return 0.0f;
    unsigned k = f2k(f);
    return (k > K || (k == K && idx <= T)) ? f : 0.0f;
}

__global__ void __launch_bounds__(NT, 3)
topk_mask_kernel(const float* __restrict__ x, float* __restrict__ out) {
    extern __shared__ char smraw[];
    SmemLayout& sm = *reinterpret_cast<SmemLayout*>(smraw);

    const int tid  = threadIdx.x;
    const int lane = tid & 31;
    const int wid  = tid >> 5;

    const size_t rowbase = (size_t)blockIdx.x * D;
    const float*  xrow = x + rowbase;
    const float4* src  = (const float4*)xrow;
    float4*       dst  = (float4*)(out + rowbase);

    // ---- init ----
    {
        unsigned* wh32 = (unsigned*)&sm.whist[0][0];   // 2048 u32
#pragma unroll
        for (int i = tid; i < 2048; i += NT) wh32[i] = 0;
        if (tid < 256) sm.hist2[tid] = 0;
        if (tid == 0)  sm.nc = 0;
    }
    __syncthreads();

    // ---- pass 1: stream row (L2-resident), u16 keys to smem, top-byte hist ----
#pragma unroll
    for (int i = 0; i < NF4; ++i) {
        float4 v = __ldcg(src + i * NT + tid);
        unsigned k0 = f2k(v.x), k1 = f2k(v.y), k2 = f2k(v.z), k3 = f2k(v.w);
        uint2 p;
        p.x = (k0 >> 16) | (k1 & 0xFFFF0000u);
        p.y = (k2 >> 16) | (k3 & 0xFFFF0000u);
        sm.keys16[i * NT + tid] = p;
        unsigned bins[4] = {k0 >> 24, k1 >> 24, k2 >> 24, k3 >> 24};
#pragma unroll
        for (int j = 0; j < 4; ++j) {
            unsigned mk = __match_any_sync(0xffffffffu, bins[j]);
            if ((unsigned)lane == (unsigned)(__ffs(mk) - 1))
                sm.whist[wid][bins[j]] =
                    (unsigned short)(sm.whist[wid][bins[j]] + __popc(mk));
        }
    }
    __syncthreads();

    // reduce per-warp hists
    if (tid < 256) {
        unsigned s = 0;
#pragma unroll
        for (int w = 0; w < NW; ++w) s += sm.whist[w][tid];
        sm.hist2[tid] = s;
    }
    __syncthreads();

    unsigned kk = TOPK;
    if (wid == 0) select_byte(sm.hist2, kk, &sm.sh_b, &sm.sh_kk, &sm.sh_ce, lane);
    __syncthreads();
    const unsigned b0 = sm.sh_b;
    kk = sm.sh_kk;

    // ---- round 1: 2nd byte hist from smem u16s ----
    if (tid < 256) sm.hist2[tid] = 0;
    __syncthreads();
#pragma unroll
    for (int i = 0; i < NF4; ++i) {
        uint2 p = sm.keys16[i * NT + tid];
        unsigned vv[4] = {p.x & 0xFFFFu, p.x >> 16, p.y & 0xFFFFu, p.y >> 16};
#pragma unroll
        for (int j = 0; j < 4; ++j)
            if ((vv[j] >> 8) == b0) atomicAdd(&sm.hist2[vv[j] & 0xFFu], 1u);
    }
    __syncthreads();
    if (wid == 0) select_byte(sm.hist2, kk, &sm.sh_b, &sm.sh_kk, &sm.sh_ce, lane);
    __syncthreads();
    const unsigned P16 = (b0 << 8) | sm.sh_b;
    unsigned kk2 = sm.sh_kk;
    const unsigned ce2 = sm.sh_ce;

    unsigned K, T;

    if (ce2 <= CAP) {
        // ---- gather the few candidates (top16 == P16), full keys from L2 ----
#pragma unroll
        for (int i = 0; i < NF4; ++i) {
            uint2 p = sm.keys16[i * NT + tid];
            unsigned base = (unsigned)(i * NT + tid) * 4u;
            unsigned vv[4] = {p.x & 0xFFFFu, p.x >> 16, p.y & 0xFFFFu, p.y >> 16};
#pragma unroll
            for (int j = 0; j < 4; ++j)
                if (vv[j] == P16) {
                    unsigned idx = base + j;
                    unsigned k   = f2k(__ldcg(xrow + idx));
                    unsigned pos = atomicAdd(&sm.nc, 1u);
                    sm.ckey[pos] = k;
                    sm.cidx[pos] = idx;
                }
        }
        __syncthreads();

        // ---- warp0: exact kth among candidates + tie index cutoff ----
        if (wid == 0) {
            unsigned n = sm.nc;
            for (unsigned j = lane; j < n; j += 32) {
                unsigned key = sm.ckey[j];
                unsigned g = 0, e = 0;
                for (unsigned q = 0; q < n; ++q) {
                    unsigned o = sm.ckey[q];
                    g += (o > key); e += (o == key);
                }
                if (g < kk2 && g + e >= kk2) {
                    sm.sh_K  = key;
                    sm.sh_kk = kk2 - g;   // m: how many == K to keep
                    sm.sh_ce = e;         // how many == K exist
                }
            }
            __syncwarp();
            unsigned Kl = sm.sh_K, m = sm.sh_kk, eK = sm.sh_ce;
            if (lane == 0 && m == eK) sm.sh_T = 0xFFFFFFFFu;
            __syncwarp();
            if (m != eK) {  // ties: keep m lowest indices among == K
                for (unsigned j = lane; j < n; j += 32)
                    if (sm.ckey[j] == Kl) {
                        unsigned r = 0;
                        for (unsigned q = 0; q < n; ++q)
                            r += (sm.ckey[q] == Kl && sm.cidx[q] < sm.cidx[j]);
                        if (r == m - 1) sm.sh_T = sm.cidx[j];
                    }
            }
        }
        __syncthreads();
        K = sm.sh_K;
        T = sm.sh_T;
    } else {
        // ---- fallback (massive ties): classic radix rounds 2,3 + bisection ----
        unsigned prefix = P16 << 16;
#pragma unroll
        for (int rr = 0; rr < 2; ++rr) {
            const int shift = 8 - 8 * rr;
            if (tid < 256) sm.hist2[tid] = 0;
            __syncthreads();
            for (int i = 0; i < NF4; ++i) {
                uint2 p = sm.keys16[i * NT + tid];
                unsigned base = (unsigned)(i * NT + tid) * 4u;
                unsigned vv[4] = {p.x & 0xFFFFu, p.x >> 16, p.y & 0xFFFFu, p.y >> 16};
                for (int j = 0; j < 4; ++j)
                    if (vv[j] == P16) {
                        unsigned k = f2k(__ldcg(xrow + base + j));
                        if ((k >> (shift + 8)) == (prefix >> (shift + 8)))
                            atomicAdd(&sm.hist2[(k >> shift) & 0xFFu], 1u);
                    }
            }
            __syncthreads();
            if (wid == 0) select_byte(sm.hist2, kk2, &sm.sh_b, &sm.sh_kk, &sm.sh_ce, lane);
            __syncthreads();
            prefix |= sm.sh_b << shift;
            kk2 = sm.sh_kk;
        }
        K = prefix;
        const unsigned m = kk2, eK = sm.sh_ce;
        T = 0xFFFFFFFFu;
        if (m != eK) {
            unsigned lo = 0, hi = D - 1;
            while (lo < hi) {
                unsigned mid = (lo + hi) >> 1;
                unsigned c = 0;
                for (int i = 0; i < NF4; ++i) {
                    uint2 p = sm.keys16[i * NT + tid];
                    unsigned base = (unsigned)(i * NT + tid) * 4u;
                    unsigned vv[4] = {p.x & 0xFFFFu, p.x >> 16, p.y & 0xFFFFu, p.y >> 16};
                    for (int j = 0; j < 4; ++j)
                        if (vv[j] == (K >> 16) && base + j <= mid) {
                            unsigned k = f2k(__ldcg(xrow + base + j));
                            c += (k == K);
                        }
                }
#pragma unroll
                for (int off = 16; off; off >>= 1)
                    c += __shfl_xor_sync(0xffffffffu, c, off);
                if (lane == 0) sm.sh_red[wid] = c;
                __syncthreads();
                if (wid == 0) {
                    unsigned t2 = (lane < NW) ? sm.sh_red[lane] : 0;
#pragma unroll
                    for (int off = 8; off; off >>= 1)
                        t2 += __shfl_xor_sync(0xffffffffu, t2, off);
                    if (lane == 0) sm.sh_red[NW] = t2;
                }
                __syncthreads();
                c = sm.sh_red[NW];
                if (c >= m) hi = mid; else lo = mid + 1;
            }
            T = lo;
        }
    }

    // ---- write pass: reload row from L2, masked streaming store ----
    const float thrF = k2f(K);
#pragma unroll
    for (int i = 0; i < NF4; ++i) {
        float4 v = __ldcg(src + i * NT + tid);
        unsigned base = (unsigned)(i * NT + tid) * 4u;
        float4 o;
        o.x = keepv(v.x, base + 0, K, T, thrF);
        o.y = keepv(v.y, base + 1, K, T, thrF);
        o.z = keepv(v.z, base + 2, K, T, thrF);
        o.w = keepv(v.w, base + 3, K, T, thrF);
        __stcs(dst + i * NT + tid, o);
    }
}

extern "C" void kernel_launch(void* const* d_in, const int* in_sizes, int n_in,
                              void* d_out, int out_size) {
    const float* x = (const float*)d_in[0];
    float* out = (float*)d_out;
    int rows = in_sizes[0] / D;
    if (rows <= 0) return;
    size_t shbytes = sizeof(SmemLayout);
    cudaFuncSetAttribute(topk_mask_kernel,
                         cudaFuncAttributeMaxDynamicSharedMemorySize,
                         (int)shbytes);
    topk_mask_kernel<<<rows, NT, shbytes>>>(x, out);
}

// round 4
// speedup vs baseline: 2.3527x; 1.2138x over previous
#include <cuda_runtime.h>
#include <cstdint>

#define D     32768          // row length
#define NT    512            // threads per CTA
#define NW    16             // warps per CTA
#define NF4   16             // float4 loads per thread (512*16*4 = 32768)
#define TOPK  32u
#define CAP   1024u          // candidate list capacity (Gaussian mean ~200)
#define THR   2.5f           // gather threshold: count(x>=2.5) ~ 200 >> 32 per row

struct Smem {
    unsigned       ckey[CAP];          // 4 KB
    unsigned short cidx[CAP];          // 2 KB
    unsigned       hist[256];          // 1 KB
    unsigned       nc;
    unsigned       sh_b, sh_kk, sh_ce, sh_T;
    unsigned       sh_red[NW + 1];
};

// order-preserving float -> uint key (larger float => larger key)
__device__ __forceinline__ unsigned f2k(float f) {
    unsigned u = __float_as_uint(f);
    return u ^ (((unsigned)((int)u >> 31)) | 0x80000000u);
}
// exact inverse
__device__ __forceinline__ float k2f(unsigned k) {
    return (k & 0x80000000u) ? __uint_as_float(k & 0x7FFFFFFFu)
                             : __uint_as_float(~k);
}

// warp0-only: pick byte b with suffix_count(b) >= kk > suffix_count(b+1).
__device__ __forceinline__ void select_byte(const unsigned* hist, unsigned kk,
                                            unsigned* sh_b, unsigned* sh_kk,
                                            unsigned* sh_ce, int lane) {
    int base = lane * 8;
    unsigned s = 0;
#pragma unroll
    for (int j = 0; j < 8; ++j) s += hist[base + j];
    unsigned suf = s;
#pragma unroll
    for (int off = 1; off < 32; off <<= 1) {
        unsigned t = __shfl_down_sync(0xffffffffu, suf, off);
        if (lane + off < 32) suf += t;
    }
    unsigned sufnext = __shfl_down_sync(0xffffffffu, suf, 1);
    if (lane == 31) sufnext = 0;
    if (suf >= kk && sufnext < kk) {   // exactly one lane
        unsigned acc = sufnext;
#pragma unroll
        for (int j = 7; j >= 0; --j) {
            unsigned t = hist[base + j];
            if (acc + t >= kk) {
                *sh_b  = (unsigned)(base + j);
                *sh_kk = kk - acc;
                *sh_ce = t;
                break;
            }
            acc += t;
        }
    }
}

__device__ __forceinline__ float keepv(float f, unsigned idx,
                                       unsigned K, unsigned T, float thrF) {
    if (f < thrF) return 0.0f;          // fast reject; exact recheck below
    unsigned k = f2k(f);
    if (k > K) return f;
    return (k == K && idx <= T) ? f : 0.0f;
}

__global__ void __launch_bounds__(NT, 4)
topk_mask_kernel(const float* __restrict__ x, float* __restrict__ out) {
    __shared__ Smem sm;

    const int tid  = threadIdx.x;
    const int lane = tid & 31;
    const int wid  = tid >> 5;

    const size_t rowbase = (size_t)blockIdx.x * D;
    const float*  xrow = x + rowbase;
    const float4* src  = (const float4*)xrow;
    float4*       dst  = (float4*)(out + rowbase);

    if (tid == 0) sm.nc = 0;
    __syncthreads();

    // ---- pass 1: stream row, warp-aggregated gather of elements >= THR ----
#pragma unroll 4
    for (int i = 0; i < NF4; ++i) {
        float4 v = __ldcg(src + i * NT + tid);
        unsigned base = (unsigned)(i * NT + tid) * 4u;
        float fv[4] = {v.x, v.y, v.z, v.w};
#pragma unroll
        for (int j = 0; j < 4; ++j) {
            bool take = !(fv[j] < THR);               // includes NaN/Inf
            unsigned mb = __ballot_sync(0xffffffffu, take);
            if (mb) {                                  // warp-uniform branch
                int leader = __ffs(mb) - 1;
                unsigned bp = 0;
                if (lane == leader) bp = atomicAdd(&sm.nc, (unsigned)__popc(mb));
                bp = __shfl_sync(0xffffffffu, bp, leader);
                if (take) {
                    unsigned pos = bp + (unsigned)__popc(mb & ((1u << lane) - 1u));
                    if (pos < CAP) {
                        sm.ckey[pos] = f2k(fv[j]);
                        sm.cidx[pos] = (unsigned short)(base + j);
                    }
                }
            }
        }
    }
    __syncthreads();

    const unsigned n = sm.nc;
    unsigned K, T = 0xFFFFFFFFu;

    if (n >= TOPK && n <= CAP) {
        // ==== fast path: exact top-k fully determined by the candidate list ====
        unsigned kk = TOPK, prefix = 0;

        // round 0 (no prefix filter)
        if (tid < 256) sm.hist[tid] = 0;
        __syncthreads();
        for (unsigned j = tid; j < n; j += NT)
            atomicAdd(&sm.hist[sm.ckey[j] >> 24], 1u);
        __syncthreads();
        if (wid == 0) select_byte(sm.hist, kk, &sm.sh_b, &sm.sh_kk, &sm.sh_ce, lane);
        __syncthreads();
        prefix = sm.sh_b << 24;
        kk = sm.sh_kk;

        // rounds 1..3
#pragma unroll
        for (int r = 1; r < 4; ++r) {
            const int shift = 24 - 8 * r;
            if (tid < 256) sm.hist[tid] = 0;
            __syncthreads();
            const unsigned ph = prefix >> (shift + 8);
            for (unsigned j = tid; j < n; j += NT) {
                unsigned k = sm.ckey[j];
                if ((k >> (shift + 8)) == ph)
                    atomicAdd(&sm.hist[(k >> shift) & 0xFFu], 1u);
            }
            __syncthreads();
            if (wid == 0) select_byte(sm.hist, kk, &sm.sh_b, &sm.sh_kk, &sm.sh_ce, lane);
            __syncthreads();
            prefix |= sm.sh_b << shift;
            kk = sm.sh_kk;
        }
        K = prefix;
        const unsigned m = kk, ce = sm.sh_ce;

        if (m != ce) {   // ties at K: T = index of the m-th smallest idx among ==K
            if (wid == 0) {
                for (unsigned j = lane; j < n; j += 32) {
                    if (sm.ckey[j] == K) {
                        unsigned idx = sm.cidx[j];
                        unsigned rless = 0;
                        for (unsigned q = 0; q < n; ++q)
                            rless += (sm.ckey[q] == K && sm.cidx[q] < idx);
                        if (rless == m - 1) sm.sh_T = idx;
                    }
                }
            }
            __syncthreads();
            T = sm.sh_T;
        }
    } else {
        // ==== fallback: exact full-width radix select from global (L2-hot) ====
        unsigned kk = TOPK, prefix = 0;
#pragma unroll
        for (int r = 0; r < 4; ++r) {
            const int shift = 24 - 8 * r;
            if (tid < 256) sm.hist[tid] = 0;
            __syncthreads();
            for (int i = 0; i < NF4; ++i) {
                float4 v = __ldcg(src + i * NT + tid);
                float fv[4] = {v.x, v.y, v.z, v.w};
#pragma unroll
                for (int j = 0; j < 4; ++j) {
                    unsigned k = f2k(fv[j]);
                    bool ok = (r == 0) ||
                              ((k >> (shift + 8)) == (prefix >> (shift + 8)) &&
                               shift + 8 < 32);
                    if (r == 0 || ((shift + 8 < 32) &&
                        (k >> (shift + 8)) == (prefix >> (shift + 8)))) {
                        (void)ok;
                        atomicAdd(&sm.hist[(k >> shift) & 0xFFu], 1u);
                    }
                }
            }
            __syncthreads();
            if (wid == 0) select_byte(sm.hist, kk, &sm.sh_b, &sm.sh_kk, &sm.sh_ce, lane);
            __syncthreads();
            prefix |= sm.sh_b << shift;
            kk = sm.sh_kk;
        }
        K = prefix;
        const unsigned m = kk, ce = sm.sh_ce;
        if (m != ce) {   // index-cutoff bisection over global data
            unsigned lo = 0, hi = D - 1;
            while (lo < hi) {
                unsigned mid = (lo + hi) >> 1;
                unsigned c = 0;
                for (int i = 0; i < NF4; ++i) {
                    float4 v = __ldcg(src + i * NT + tid);
                    unsigned base = (unsigned)(i * NT + tid) * 4u;
                    float fv[4] = {v.x, v.y, v.z, v.w};
#pragma unroll
                    for (int j = 0; j < 4; ++j)
                        c += (f2k(fv[j]) == K && base + j <= mid);
                }
#pragma unroll
                for (int off = 16; off; off >>= 1)
                    c += __shfl_xor_sync(0xffffffffu, c, off);
                if (lane == 0) sm.sh_red[wid] = c;
                __syncthreads();
                if (wid == 0) {
                    unsigned t2 = (lane < NW) ? sm.sh_red[lane] : 0;
#pragma unroll
                    for (int off = 8; off; off >>= 1)
                        t2 += __shfl_xor_sync(0xffffffffu, t2, off);
                    if (lane == 0) sm.sh_red[NW] = t2;
                }
                __syncthreads();
                c = sm.sh_red[NW];
                if (c >= m) hi = mid; else lo = mid + 1;
            }
            T = lo;
        }
    }

    // ---- write pass: reload row from L2, masked streaming store ----
    const float thrF = k2f(K);
#pragma unroll 4
    for (int i = 0; i < NF4; ++i) {
        float4 v = __ldcg(src + i * NT + tid);
        unsigned base = (unsigned)(i * NT + tid) * 4u;
        float4 o;
        o.x = keepv(v.x, base + 0, K, T, thrF);
        o.y = keepv(v.y, base + 1, K, T, thrF);
        o.z = keepv(v.z, base + 2, K, T, thrF);
        o.w = keepv(v.w, base + 3, K, T, thrF);
        __stcs(dst + i * NT + tid, o);
    }
}

extern "C" void kernel_launch(void* const* d_in, const int* in_sizes, int n_in,
                              void* d_out, int out_size) {
    const float* x = (const float*)d_in[0];
    float* out = (float*)d_out;
    int rows = in_sizes[0] / D;
    if (rows <= 0) return;
    topk_mask_kernel<<<rows, NT>>>(x, out);
}

// round 6
// speedup vs baseline: 3.1792x; 1.3513x over previous
#include <cuda_runtime.h>
#include <cstdint>

#define D     32768          // row length
#define NT    512            // threads per CTA
#define NW    16             // warps per CTA
#define NF4   16             // float4 loads per thread (512*16*4 = 32768)
#define TOPK  32u
#define CAP   1024u          // candidate capacity (Gaussian mean ~200)
#define THR   2.5f           // gather threshold: E[count(x>=2.5)] ~ 200 >> 32 per row

struct Smem {
    unsigned       ckey[CAP];          // 4 KB
    unsigned short cidx[CAP];          // 2 KB
    unsigned       hist[256];          // 1 KB
    unsigned       nc;
    unsigned       sh_b, sh_kk, sh_ce;
    unsigned       sh_K, sh_T;
    unsigned       sh_red[NW + 1];
};

// order-preserving float -> uint key (larger float => larger key); bijective
__device__ __forceinline__ unsigned f2k(float f) {
    unsigned u = __float_as_uint(f);
    return u ^ (((unsigned)((int)u >> 31)) | 0x80000000u);
}
// exact inverse of f2k
__device__ __forceinline__ float k2f(unsigned k) {
    return (k & 0x80000000u) ? __uint_as_float(k & 0x7FFFFFFFu)
                             : __uint_as_float(~k);
}

// warp-collective: pick byte b with suffix_count(b) >= kk > suffix_count(b+1).
__device__ __forceinline__ void select_byte(const unsigned* hist, unsigned kk,
                                            unsigned* sh_b, unsigned* sh_kk,
                                            unsigned* sh_ce, int lane) {
    int base = lane * 8;
    unsigned s = 0;
#pragma unroll
    for (int j = 0; j < 8; ++j) s += hist[base + j];
    unsigned suf = s;
#pragma unroll
    for (int off = 1; off < 32; off <<= 1) {
        unsigned t = __shfl_down_sync(0xffffffffu, suf, off);
        if (lane + off < 32) suf += t;
    }
    unsigned sufnext = __shfl_down_sync(0xffffffffu, suf, 1);
    if (lane == 31) sufnext = 0;
    if (suf >= kk && sufnext < kk) {   // exactly one lane
        unsigned acc = sufnext;
#pragma unroll
        for (int j = 7; j >= 0; --j) {
            unsigned t = hist[base + j];
            if (acc + t >= kk) {
                *sh_b  = (unsigned)(base + j);
                *sh_kk = kk - acc;
                *sh_ce = t;
                break;
            }
            acc += t;
        }
    }
}

__device__ __forceinline__ float keepv(float f, unsigned idx,
                                       unsigned K, unsigned T) {
    unsigned k = f2k(f);
    if (k > K) return f;
    return (k == K && idx <= T) ? f : 0.0f;
}

__global__ void __launch_bounds__(NT, 4)
topk_mask_kernel(const float* __restrict__ x, float* __restrict__ out) {
    __shared__ Smem sm;

    const int tid  = threadIdx.x;
    const int lane = tid & 31;
    const int wid  = tid >> 5;

    const size_t rowbase = (size_t)blockIdx.x * D;
    const float*  xrow = x + rowbase;
    float*        orow = out + rowbase;
    const float4* src  = (const float4*)xrow;
    float4*       dst  = (float4*)orow;

    if (tid == 0) sm.nc = 0;
    __syncthreads();

    // ---- pass 1 (fused): stream row once, gather candidates (rare),
    //      and stream zeros to the output concurrently ----
    const float4 z4 = make_float4(0.f, 0.f, 0.f, 0.f);
#pragma unroll 4
    for (int i = 0; i < NF4; ++i) {
        float4 v = __ldcg(src + i * NT + tid);
        __stcs(dst + i * NT + tid, z4);               // independent store stream
        // candidate test: !(f < THR) also catches NaN/Inf
        bool t0 = !(v.x < THR), t1 = !(v.y < THR);
        bool t2 = !(v.z < THR), t3 = !(v.w < THR);
        if (t0 | t1 | t2 | t3) {                       // rare (~2.4% of threads)
            unsigned base = (unsigned)(i * NT + tid) * 4u;
            float fv[4] = {v.x, v.y, v.z, v.w};
            bool  tk[4] = {t0, t1, t2, t3};
#pragma unroll
            for (int j = 0; j < 4; ++j)
                if (tk[j]) {
                    unsigned pos = atomicAdd(&sm.nc, 1u);
                    if (pos < CAP) {
                        sm.ckey[pos] = f2k(fv[j]);
                        sm.cidx[pos] = (unsigned short)(base + j);
                    }
                }
        }
    }
    __syncthreads();   // orders all zero-stores before the scatter below

    const unsigned n = sm.nc;
    const bool fast = (n >= TOPK && n <= CAP);

    if (fast) {
        // ==== warp0-only exact selection over the candidate list ====
        if (wid == 0) {
            unsigned kk = TOPK, prefix = 0;
#pragma unroll
            for (int r = 0; r < 4; ++r) {
                const int shift = 24 - 8 * r;
                for (int j = lane; j < 256; j += 32) sm.hist[j] = 0;
                __syncwarp();
                for (unsigned j = lane; j < n; j += 32) {
                    unsigned k = sm.ckey[j];
                    // ((k>>shift)>>8) avoids the shift-by-32 case at r==0
                    if (r == 0 || ((k >> shift) >> 8) == ((prefix >> shift) >> 8))
                        atomicAdd(&sm.hist[(k >> shift) & 0xFFu], 1u);
                }
                __syncwarp();
                select_byte(sm.hist, kk, &sm.sh_b, &sm.sh_kk, &sm.sh_ce, lane);
                __syncwarp();
                prefix |= sm.sh_b << shift;
                kk = sm.sh_kk;
            }
            const unsigned m = kk, ce = sm.sh_ce;
            if (lane == 0) {
                sm.sh_K = prefix;
                if (m == ce) sm.sh_T = 0xFFFFFFFFu;
            }
            __syncwarp();
            if (m != ce) {  // ties at K: T = idx of the m-th smallest index among ==K
                for (unsigned j = lane; j < n; j += 32)
                    if (sm.ckey[j] == prefix) {
                        unsigned idx = sm.cidx[j];
                        unsigned rless = 0;
                        for (unsigned q = 0; q < n; ++q)
                            rless += (sm.ckey[q] == prefix && sm.cidx[q] < idx);
                        if (rless == m - 1) sm.sh_T = idx;
                    }
            }
        }
        __syncthreads();
        const unsigned K = sm.sh_K, T = sm.sh_T;

        // ==== scatter winners over the zeros (<=CAP checks, <=k stores) ====
        for (unsigned j = tid; j < n; j += NT) {
            unsigned k = sm.ckey[j];
            if (k > K || (k == K && sm.cidx[j] <= T))
                orow[sm.cidx[j]] = k2f(k);
        }
    } else {
        // ==== exact fallback for any input: full-width radix from global ====
        unsigned kk = TOPK, prefix = 0;
#pragma unroll
        for (int r = 0; r < 4; ++r) {
            const int shift = 24 - 8 * r;
            if (tid < 256) sm.hist[tid] = 0;
            __syncthreads();
            for (int i = 0; i < NF4; ++i) {
                float4 v = __ldcg(src + i * NT + tid);
                float fv[4] = {v.x, v.y, v.z, v.w};
#pragma unroll
                for (int j = 0; j < 4; ++j) {
                    unsigned k = f2k(fv[j]);
                    if (r == 0 || ((k >> shift) >> 8) == ((prefix >> shift) >> 8))
                        atomicAdd(&sm.hist[(k >> shift) & 0xFFu], 1u);
                }
            }
            __syncthreads();
            if (wid == 0) select_byte(sm.hist, kk, &sm.sh_b, &sm.sh_kk, &sm.sh_ce, lane);
            __syncthreads();
            prefix |= sm.sh_b << shift;
            kk = sm.sh_kk;
        }
        unsigned K = prefix, T = 0xFFFFFFFFu;
        const unsigned m = kk, ce = sm.sh_ce;
        if (m != ce) {   // index-cutoff bisection over global data
            unsigned lo = 0, hi = D - 1;
            while (lo < hi) {
                unsigned mid = (lo + hi) >> 1;
                unsigned c = 0;
                for (int i = 0; i < NF4; ++i) {
                    float4 v = __ldcg(src + i * NT + tid);
                    unsigned base = (unsigned)(i * NT + tid) * 4u;
                    float fv[4] = {v.x, v.y, v.z, v.w};
#pragma unroll
                    for (int j = 0; j < 4; ++j)
                        c += (f2k(fv[j]) == K && base + j <= mid);
                }
#pragma unroll
                for (int off = 16; off; off >>= 1)
                    c += __shfl_xor_sync(0xffffffffu, c, off);
                if (lane == 0) sm.sh_red[wid] = c;
                __syncthreads();
                if (wid == 0) {
                    unsigned t2 = (lane < NW) ? sm.sh_red[lane] : 0;
#pragma unroll
                    for (int off = 8; off; off >>= 1)
                        t2 += __shfl_xor_sync(0xffffffffu, t2, off);
                    if (lane == 0) sm.sh_red[NW] = t2;
                }
                __syncthreads();
                c = sm.sh_red[NW];
                if (c >= m) hi = mid; else lo = mid + 1;
            }
            T = lo;
        }
        // full masked rewrite (overwrites the zeros; correct for any input)
        for (int i = 0; i < NF4; ++i) {
            float4 v = __ldcg(src + i * NT + tid);
            unsigned base = (unsigned)(i * NT + tid) * 4u;
            float4 o;
            o.x = keepv(v.x, base + 0, K, T);
            o.y = keepv(v.y, base + 1, K, T);
            o.z = keepv(v.z, base + 2, K, T);
            o.w = keepv(v.w, base + 3, K, T);
            __stcs(dst + i * NT + tid, o);
        }
    }
}

extern "C" void kernel_launch(void* const* d_in, const int* in_sizes, int n_in,
                              void* d_out, int out_size) {
    const float* x = (const float*)d_in[0];
    float* out = (float*)d_out;
    int rows = in_sizes[0] / D;
    if (rows <= 0) return;
    topk_mask_kernel<<<rows, NT>>>(x, out);
}